// round 11
// baseline (speedup 1.0000x reference)
#include <cuda_runtime.h>
#include <stdint.h>

// ---------------- problem constants ----------------
#define NB     16
#define NPROP  2000
#define NGT    100
#define NPOS   66
#define NNEG   134
#define NROI   200
#define HH     160
#define WW     160
#define MH     28
#define MW     28

// output layout (float32, concatenated flattened tuple)
#define ROIS_OFF 0
#define CLS_OFF  (NB*NROI*4)                 // 12800
#define DEL_OFF  (CLS_OFF + NB*NROI)         // 16000
#define MSK_OFF  (DEL_OFF + NB*NROI*4)       // 28800

// ---------------- scratch (__device__ globals; no allocs allowed) ----------------
__device__ float         g_ioumax[NB*NPROP];
__device__ int           g_ioarg [NB*NPROP];
__device__ unsigned char g_pvalid[NB*NPROP];
__device__ float         g_posbox[NB*NPOS*4];
__device__ int           g_posgt [NB*NPOS];   // gt index, -1 if slot invalid

// ---------------- JAX threefry2x32 (partitionable-default semantics) ----------------
__device__ __forceinline__ void tf2x32(uint32_t k0, uint32_t k1,
                                       uint32_t x0, uint32_t x1,
                                       uint32_t &o0, uint32_t &o1) {
    uint32_t ks2 = k0 ^ k1 ^ 0x1BD11BDAu;
    x0 += k0; x1 += k1;
#define TF_RND(r) { x0 += x1; x1 = __funnelshift_l(x1, x1, (r)); x1 ^= x0; }
    TF_RND(13) TF_RND(15) TF_RND(26) TF_RND(6)
    x0 += k1;  x1 += ks2 + 1u;
    TF_RND(17) TF_RND(29) TF_RND(16) TF_RND(24)
    x0 += ks2; x1 += k0 + 2u;
    TF_RND(13) TF_RND(15) TF_RND(26) TF_RND(6)
    x0 += k0;  x1 += k1 + 3u;
    TF_RND(17) TF_RND(29) TF_RND(16) TF_RND(24)
    x0 += k1;  x1 += ks2 + 4u;
    TF_RND(13) TF_RND(15) TF_RND(26) TF_RND(6)
    x0 += ks2; x1 += k0 + 5u;
#undef TF_RND
    o0 = x0; o1 = x1;
}

// jax.random.uniform(key, ()) element i, partitionable path: bits = o0 ^ o1 of
// threefry(key, (hi=0, lo=i)); u = bitcast((bits>>9)|0x3f800000) - 1
__device__ __forceinline__ float jax_uniform(uint32_t k0, uint32_t k1, uint32_t i) {
    uint32_t a, b;
    tf2x32(k0, k1, 0u, i, a, b);
    uint32_t bits = a ^ b;
    return __uint_as_float((bits >> 9) | 0x3f800000u) - 1.0f;
}

// ---------------- Kernel 0: per-proposal IoU max / argmax ----------------
__global__ void k_iou(const float* __restrict__ prop,
                      const int*   __restrict__ gcls,
                      const float* __restrict__ gbox) {
    __shared__ float sg[NGT*4];
    __shared__ int   sc[NGT];
    int b = blockIdx.y;
    for (int t = threadIdx.x; t < NGT*4; t += blockDim.x) sg[t] = gbox[b*NGT*4 + t];
    for (int t = threadIdx.x; t < NGT;   t += blockDim.x) sc[t] = gcls[b*NGT + t];
    __syncthreads();
    int i = blockIdx.x * blockDim.x + threadIdx.x;
    if (i >= NPROP) return;
    const float4 p = *reinterpret_cast<const float4*>(prop + (size_t)(b*NPROP + i)*4);
    bool valid = (p.x != 0.f) || (p.y != 0.f) || (p.z != 0.f) || (p.w != 0.f);
    float a1 = (p.z - p.x) * (p.w - p.y);
    float best = -1.0f; int arg = 0;
    #pragma unroll 4
    for (int g = 0; g < NGT; g++) {
        if (sc[g] <= 0) continue;   // masked gts have value -1.0 -> never exceed best
        float gy1 = sg[g*4+0], gx1 = sg[g*4+1], gy2 = sg[g*4+2], gx2 = sg[g*4+3];
        float yA = fmaxf(p.x, gy1), xA = fmaxf(p.y, gx1);
        float yB = fminf(p.z, gy2), xB = fminf(p.w, gx2);
        float inter = fmaxf(yB - yA, 0.f) * fmaxf(xB - xA, 0.f);
        float a2 = (gy2 - gy1) * (gx2 - gx1);
        float uni = fmaxf(a1 + a2 - inter, 1e-10f);
        float iou = inter / uni;
        if (iou > best) { best = iou; arg = g; }  // strict > == argmax first-max
    }
    g_ioumax[b*NPROP+i] = best;
    g_ioarg [b*NPROP+i] = arg;
    g_pvalid[b*NPROP+i] = valid ? 1 : 0;
}

// ---------------- bitonic sort: 2048 pairs, descending score, idx tie ascending ----------------
__device__ void bitonic2048(float* ss, int* si, int tid) {
    for (int k = 2; k <= 2048; k <<= 1) {
        for (int j = k >> 1; j > 0; j >>= 1) {
            __syncthreads();
            #pragma unroll 2
            for (int t = tid; t < 1024; t += 512) {
                int i  = ((t & ~(j-1)) << 1) | (t & (j-1));
                int ix = i | j;
                float s1 = ss[i], s2 = ss[ix];
                int   a1 = si[i], a2 = si[ix];
                bool bef  = (s1 > s2) || (s1 == s2 && a1 < a2); // s1 should precede s2 (desc)
                bool desc = ((i & k) == 0);
                if (bef != desc) { ss[i] = s2; ss[ix] = s1; si[i] = a2; si[ix] = a1; }
            }
        }
    }
    __syncthreads();
}

// ---------------- Kernel 1: sampling + rois/class/deltas ----------------
__global__ __launch_bounds__(512) void k_sample(const float* __restrict__ prop,
                                                const int*   __restrict__ gcls,
                                                const float* __restrict__ gbox,
                                                const float* __restrict__ stddev,
                                                float*       __restrict__ out) {
    __shared__ float ss[2048];
    __shared__ int   si[2048];
    __shared__ int   sP;
    __shared__ int   sposidx[NPOS];
    __shared__ int   sposval[NPOS];
    int b = blockIdx.x, tid = threadIdx.x;

    // key chain: root=(0,42); keys[b]=tf(root,(0,b)); kp=tf(kb,(0,0)); kn=tf(kb,(0,1))
    uint32_t kb0, kb1, kp0, kp1, kn0, kn1;
    tf2x32(0u, 42u, 0u, (uint32_t)b, kb0, kb1);
    tf2x32(kb0, kb1, 0u, 0u, kp0, kp1);
    tf2x32(kb0, kb1, 0u, 1u, kn0, kn1);

    // ---- pass 1: positive candidate scores ----
    for (int i = tid; i < 2048; i += 512) {
        float sc = -3.0f;
        if (i < NPROP) {
            float m  = g_ioumax[b*NPROP+i];
            bool pos = (m >= 0.5f) && g_pvalid[b*NPROP+i];
            sc = pos ? jax_uniform(kp0, kp1, (uint32_t)i) : -1.0f;
        }
        ss[i] = sc; si[i] = i;
    }
    bitonic2048(ss, si, tid);

    if (tid < NPOS) { sposidx[tid] = si[tid]; sposval[tid] = (ss[tid] > 0.0f) ? 1 : 0; }
    __syncthreads();
    if (tid == 0) { int P = 0; for (int t = 0; t < NPOS; t++) P += sposval[t]; sP = P; }

    // ---- rebuild buffer with negative scores (overwrites ss/si) ----
    for (int i = tid; i < 2048; i += 512) {
        float sc = -3.0f;
        if (i < NPROP) {
            float m  = g_ioumax[b*NPROP+i];
            bool neg = (m < 0.5f) && g_pvalid[b*NPROP+i];
            sc = neg ? jax_uniform(kn0, kn1, (uint32_t)i) : -1.0f;
        }
        ss[i] = sc; si[i] = i;
    }

    // ---- write positive outputs (uses only sposidx/sposval + globals) ----
    if (tid < NPOS) {
        int  t     = tid;
        int  idx   = sposidx[t];
        bool valid = sposval[t] != 0;
        const float4 p = *reinterpret_cast<const float4*>(prop + (size_t)(b*NPROP + idx)*4);
        int g = g_ioarg[b*NPROP+idx];

        float* r = out + ROIS_OFF + (size_t)(b*NROI + t)*4;
        r[0] = valid ? p.x : 0.f; r[1] = valid ? p.y : 0.f;
        r[2] = valid ? p.z : 0.f; r[3] = valid ? p.w : 0.f;

        float d0 = 0.f, d1 = 0.f, d2 = 0.f, d3 = 0.f;
        int cls = 0;
        if (valid) {
            const float4 gb = *reinterpret_cast<const float4*>(gbox + (size_t)(b*NGT + g)*4);
            cls = gcls[b*NGT + g];
            float h  = p.z - p.x,  w  = p.w - p.y;
            float cy = p.x + 0.5f*h, cx = p.y + 0.5f*w;
            float gh = gb.z - gb.x, gw = gb.w - gb.y;
            float gcy = gb.x + 0.5f*gh, gcx = gb.y + 0.5f*gw;
            d0 = __fdiv_rn(__fdiv_rn(gcy - cy, h), stddev[0]);
            d1 = __fdiv_rn(__fdiv_rn(gcx - cx, w), stddev[1]);
            d2 = __fdiv_rn(logf(__fdiv_rn(gh, h)), stddev[2]);
            d3 = __fdiv_rn(logf(__fdiv_rn(gw, w)), stddev[3]);
        }
        out[CLS_OFF + b*NROI + t] = (float)cls;
        float* d = out + DEL_OFF + (size_t)(b*NROI + t)*4;
        d[0] = d0; d[1] = d1; d[2] = d2; d[3] = d3;

        g_posbox[(b*NPOS + t)*4 + 0] = p.x;
        g_posbox[(b*NPOS + t)*4 + 1] = p.y;
        g_posbox[(b*NPOS + t)*4 + 2] = p.z;
        g_posbox[(b*NPOS + t)*4 + 3] = p.w;
        g_posgt[b*NPOS + t] = valid ? g : -1;
    }

    bitonic2048(ss, si, tid);   // sort negatives (first internal sync orders sP & rebuild)

    // ---- negatives ----
    // XLA rewrites x / const -> x * (1/const). fl32(1/0.33f) = 12710012 * 2^-22.
    // For P=66: 66 * 3.0303030014f -> exactly 200.0f -> trunc 200 -> needed 134.
    // (IEEE division would give 199.99998474 -> 199 -> 133: one row short.)
    int P = sP;
    const float recip033 = 3.03030300140380859375f;  // fl32(1.0f / 0.33f)
    float nnf = __fmul_rn((float)P, recip033);
    int needed = (int)nnf - P;                       // truncation toward zero (astype int32)
    needed = min(max(needed, 0), NNEG);
    for (int t = tid; t < NNEG; t += 512) {
        bool valid = (ss[t] > 0.0f) && (t < needed);
        float4 p = make_float4(0.f, 0.f, 0.f, 0.f);
        if (valid) p = *reinterpret_cast<const float4*>(prop + (size_t)(b*NPROP + si[t])*4);
        int slot = NPOS + t;
        float* r = out + ROIS_OFF + (size_t)(b*NROI + slot)*4;
        r[0] = p.x; r[1] = p.y; r[2] = p.z; r[3] = p.w;
        out[CLS_OFF + b*NROI + slot] = 0.f;
        float* d = out + DEL_OFF + (size_t)(b*NROI + slot)*4;
        d[0] = 0.f; d[1] = 0.f; d[2] = 0.f; d[3] = 0.f;
    }
}

// ---------------- Kernel 2: mask crop_and_resize ----------------
__global__ void k_mask(const float* __restrict__ masks, float* __restrict__ out) {
    int b = blockIdx.y, slot = blockIdx.x;
    float* o = out + MSK_OFF + (size_t)(b*NROI + slot)*(MH*MW);
    int g = -1;
    float y1 = 0.f, x1 = 0.f, y2 = 0.f, x2 = 0.f;
    if (slot < NPOS) {
        g  = g_posgt[b*NPOS + slot];
        y1 = g_posbox[(b*NPOS + slot)*4 + 0];
        x1 = g_posbox[(b*NPOS + slot)*4 + 1];
        y2 = g_posbox[(b*NPOS + slot)*4 + 2];
        x2 = g_posbox[(b*NPOS + slot)*4 + 3];
    }
    if (g < 0) {
        for (int p = threadIdx.x; p < MH*MW; p += blockDim.x) o[p] = 0.f;
        return;
    }
    const float* img = masks + (size_t)b*HH*WW*NGT + g;
    for (int p = threadIdx.x; p < MH*MW; p += blockDim.x) {
        int i = p / MW, j = p % MW;
        float ty = __fdiv_rn((float)i, (float)(MH - 1));
        float tx = __fdiv_rn((float)j, (float)(MW - 1));
        float ys = (y1 + ty * (y2 - y1)) * (float)(HH - 1);
        float xs = (x1 + tx * (x2 - x1)) * (float)(WW - 1);
        float y0f = floorf(ys), x0f = floorf(xs);
        float fy = ys - y0f,    fx = xs - x0f;
        int y0  = min(max((int)y0f, 0), HH - 1);
        int y1i = min(y0 + 1, HH - 1);
        int x0  = min(max((int)x0f, 0), WW - 1);
        int x1i = min(x0 + 1, WW - 1);
        float m00 = __ldg(img + ((size_t)y0 *WW + x0 )*NGT);
        float m01 = __ldg(img + ((size_t)y0 *WW + x1i)*NGT);
        float m10 = __ldg(img + ((size_t)y1i*WW + x0 )*NGT);
        float m11 = __ldg(img + ((size_t)y1i*WW + x1i)*NGT);
        float v = m00*(1.f-fy)*(1.f-fx) + m01*(1.f-fy)*fx
                + m10*fy*(1.f-fx)       + m11*fy*fx;
        o[p] = rintf(v);   // jnp.round = round half to even
    }
}

// ---------------- launch ----------------
extern "C" void kernel_launch(void* const* d_in, const int* in_sizes, int n_in,
                              void* d_out, int out_size) {
    (void)in_sizes; (void)n_in; (void)out_size;
    const float* prop   = (const float*)d_in[0];
    const int*   cls    = (const int*)  d_in[1];
    const float* gbox   = (const float*)d_in[2];
    const float* masks  = (const float*)d_in[3];
    const float* stddev = (const float*)d_in[4];
    float* out = (float*)d_out;

    k_iou   <<<dim3(8, NB),    256>>>(prop, cls, gbox);
    k_sample<<<NB,             512>>>(prop, cls, gbox, stddev, out);
    k_mask  <<<dim3(NROI, NB), 256>>>(masks, out);
}

// round 13
// speedup vs baseline: 1.7873x; 1.7873x over previous
#include <cuda_runtime.h>
#include <stdint.h>

// ---------------- problem constants ----------------
#define NB     16
#define NPROP  2000
#define NGT    100
#define NPOS   66
#define NNEG   134
#define NROI   200
#define HH     160
#define WW     160
#define MH     28
#define MW     28

// output layout (float32, concatenated flattened tuple)
#define ROIS_OFF 0
#define CLS_OFF  (NB*NROI*4)                 // 12800
#define DEL_OFF  (CLS_OFF + NB*NROI)         // 16000
#define MSK_OFF  (DEL_OFF + NB*NROI*4)       // 28800

// ---------------- scratch (__device__ globals; no allocs allowed) ----------------
__device__ float         g_ioumax[NB*NPROP];
__device__ int           g_ioarg [NB*NPROP];
__device__ unsigned char g_pvalid[NB*NPROP];
__device__ float         g_posbox[NB*NPOS*4];
__device__ int           g_posgt [NB*NPOS];   // gt index, -1 if slot invalid

// ---------------- JAX threefry2x32 (partitionable-default semantics) ----------------
__device__ __forceinline__ void tf2x32(uint32_t k0, uint32_t k1,
                                       uint32_t x0, uint32_t x1,
                                       uint32_t &o0, uint32_t &o1) {
    uint32_t ks2 = k0 ^ k1 ^ 0x1BD11BDAu;
    x0 += k0; x1 += k1;
#define TF_RND(r) { x0 += x1; x1 = __funnelshift_l(x1, x1, (r)); x1 ^= x0; }
    TF_RND(13) TF_RND(15) TF_RND(26) TF_RND(6)
    x0 += k1;  x1 += ks2 + 1u;
    TF_RND(17) TF_RND(29) TF_RND(16) TF_RND(24)
    x0 += ks2; x1 += k0 + 2u;
    TF_RND(13) TF_RND(15) TF_RND(26) TF_RND(6)
    x0 += k0;  x1 += k1 + 3u;
    TF_RND(17) TF_RND(29) TF_RND(16) TF_RND(24)
    x0 += k1;  x1 += ks2 + 4u;
    TF_RND(13) TF_RND(15) TF_RND(26) TF_RND(6)
    x0 += ks2; x1 += k0 + 5u;
#undef TF_RND
    o0 = x0; o1 = x1;
}

__device__ __forceinline__ float jax_uniform(uint32_t k0, uint32_t k1, uint32_t i) {
    uint32_t a, b;
    tf2x32(k0, k1, 0u, i, a, b);
    uint32_t bits = a ^ b;
    return __uint_as_float((bits >> 9) | 0x3f800000u) - 1.0f;
}

// ---------------- Kernel 0: per-proposal IoU max / argmax ----------------
// 4 lanes per proposal (25 GTs each), division-free tracking via rational
// (inter, uni) with safe-margin cross-multiplication compare; rare fallback
// to exact __fdiv_rn keeps selection bit-identical to rounded-quotient argmax.
__global__ __launch_bounds__(256) void k_iou(const float* __restrict__ prop,
                                             const int*   __restrict__ gcls,
                                             const float* __restrict__ gbox) {
    __shared__ float4 sg4[NGT];
    __shared__ float  sa [NGT];   // gt area, NaN if class invalid
    int b = blockIdx.y, tid = threadIdx.x;
    for (int t = tid; t < NGT; t += 256) {
        float4 g = *reinterpret_cast<const float4*>(gbox + (size_t)(b*NGT + t)*4);
        sg4[t] = g;
        float a2 = (g.z - g.x) * (g.w - g.y);
        sa[t] = (gcls[b*NGT + t] > 0) ? a2 : __int_as_float(0x7FC00000);  // NaN
    }
    __syncthreads();

    int gi = blockIdx.x * 64 + (tid >> 2);   // proposal index within image
    int r  = tid & 3;                        // gt-quarter
    if (gi >= NPROP) return;

    const float4 p = *reinterpret_cast<const float4*>(prop + (size_t)(b*NPROP + gi)*4);
    float a1 = (p.z - p.x) * (p.w - p.y);

    float ib = -1.0f, ub = 1.0f;             // best as rational: q = ib/ub
    int   arg = r * 25;
    const float UP = 1.0f + 2e-6f, DN = 1.0f - 2e-6f;

    #pragma unroll 5
    for (int k = 0; k < 25; k++) {
        int g = r * 25 + k;
        float4 gb = sg4[g];
        float a2 = sa[g];
        float yA = fmaxf(p.x, gb.x), xA = fmaxf(p.y, gb.y);
        float yB = fminf(p.z, gb.z), xB = fminf(p.w, gb.w);
        float inter = fmaxf(yB - yA, 0.f) * fmaxf(xB - xA, 0.f);
        float uni = fmaxf(a1 + a2 - inter, 1e-10f);    // NaN a2 -> uni = 1e-10 BUT gated by gok
        bool gok = (a2 == a2);
        if (inter == 0.0f) {
            if (gok && ib < 0.0f) { ib = 0.0f; ub = uni; arg = g; }   // q=0 beats -1 only
        } else if (gok) {
            float c1 = __fmul_rn(inter, ub);
            float c2 = __fmul_rn(ib, uni);
            if (c1 > __fmul_rn(c2, UP)) {              // provably RN(qn) > RN(qb)
                ib = inter; ub = uni; arg = g;
            } else if (c1 >= __fmul_rn(c2, DN)) {      // ambiguous band: exact check
                float qn = __fdiv_rn(inter, uni);
                float qb = __fdiv_rn(ib, ub);
                if (qn > qb) { ib = inter; ub = uni; arg = g; }
            } // else provably qn_exact < qb_exact -> RN(qn) <= RN(qb) -> no update
        }
    }
    // segment value (exactly max of rounded quotients in this segment)
    float q = __fdiv_rn(ib, ub);   // -1/1=-1, 0/u=0, else quotient

    // merge 4 segments: max value, tie -> min gt index (== argmax-first)
    #pragma unroll
    for (int off = 1; off < 4; off <<= 1) {
        float q2 = __shfl_down_sync(0xFFFFFFFFu, q,   off, 4);
        int   a2 = __shfl_down_sync(0xFFFFFFFFu, arg, off, 4);
        if (q2 > q || (q2 == q && a2 < arg)) { q = q2; arg = a2; }
    }
    if (r == 0) {
        bool valid = (p.x != 0.f) || (p.y != 0.f) || (p.z != 0.f) || (p.w != 0.f);
        g_ioumax[b*NPROP + gi] = q;
        g_ioarg [b*NPROP + gi] = arg;
        g_pvalid[b*NPROP + gi] = valid ? 1 : 0;
    }
}

// ---------------- bitonic sort: 2048 64-bit keys, DESCENDING ----------------
// key = (monotonic_map(score) << 32) | (0xFFFFFFFF - idx)  => descending sort
// gives descending score with ascending index tie-break (== lax.top_k order).
__device__ void bsort2048(unsigned long long* sk, int tid) {
    for (int k = 2; k <= 2048; k <<= 1) {
        for (int j = k >> 1; j > 0; j >>= 1) {
            __syncthreads();
            #pragma unroll 2
            for (int t = tid; t < 1024; t += 512) {
                int i  = ((t & ~(j-1)) << 1) | (t & (j-1));
                int ix = i | j;
                unsigned long long A = sk[i], B = sk[ix];
                bool desc = ((i & k) == 0);
                if ((A < B) == desc) { sk[i] = B; sk[ix] = A; }
            }
        }
    }
    __syncthreads();
}

__device__ __forceinline__ uint32_t fmap(float f) {
    uint32_t u = __float_as_uint(f);
    return (u >> 31) ? ~u : (u | 0x80000000u);
}

// ---------------- Kernel 1: sampling. grid = (image, role[pos|neg]) ----------------
__global__ __launch_bounds__(512) void k_sample(const float* __restrict__ prop,
                                                const int*   __restrict__ gcls,
                                                const float* __restrict__ gbox,
                                                const float* __restrict__ stddev,
                                                float*       __restrict__ out) {
    __shared__ unsigned long long sk[2048];
    __shared__ int scnt;
    int b = blockIdx.x, role = blockIdx.y, tid = threadIdx.x;

    uint32_t kb0, kb1, kp0, kp1, kn0, kn1;
    tf2x32(0u, 42u, 0u, (uint32_t)b, kb0, kb1);
    tf2x32(kb0, kb1, 0u, 0u, kp0, kp1);
    tf2x32(kb0, kb1, 0u, 1u, kn0, kn1);

    uint32_t sk0 = role ? kn0 : kp0, sk1 = role ? kn1 : kp1;
    if (tid == 0) scnt = 0;

    // build keys (+ neg role counts positives for P)
    int cnt = 0;
    for (int i = tid; i < 2048; i += 512) {
        uint32_t key32 = 0;                      // filler: sorts last
        if (i < NPROP) {
            float m = g_ioumax[b*NPROP + i];
            bool  v = g_pvalid[b*NPROP + i] != 0;
            bool pos = (m >= 0.5f) && v;
            bool cand = role ? ((m < 0.5f) && v) : pos;
            float sc = cand ? jax_uniform(sk0, sk1, (uint32_t)i) : -1.0f;
            key32 = fmap(sc);
            if (role && pos && jax_uniform(kp0, kp1, (uint32_t)i) > 0.0f) cnt++;
        }
        sk[i] = ((unsigned long long)key32 << 32) | (uint32_t)(0xFFFFFFFFu - (uint32_t)i);
    }
    if (role && cnt) atomicAdd(&scnt, cnt);

    bsort2048(sk, tid);   // internal barriers also publish scnt

    if (role == 0) {
        // ---- positives: slots [0,66) ----
        if (tid < NPOS) {
            int t = tid;
            unsigned long long key = sk[t];
            bool valid = (uint32_t)(key >> 32) > 0x80000000u;   // score > 0
            int  idx   = (int)(0xFFFFFFFFu - (uint32_t)key);
            const float4 p = *reinterpret_cast<const float4*>(prop + (size_t)(b*NPROP + idx)*4);
            int g = g_ioarg[b*NPROP + idx];

            float* rr = out + ROIS_OFF + (size_t)(b*NROI + t)*4;
            rr[0] = valid ? p.x : 0.f; rr[1] = valid ? p.y : 0.f;
            rr[2] = valid ? p.z : 0.f; rr[3] = valid ? p.w : 0.f;

            float d0 = 0.f, d1 = 0.f, d2 = 0.f, d3 = 0.f;
            int cls = 0;
            if (valid) {
                const float4 gb = *reinterpret_cast<const float4*>(gbox + (size_t)(b*NGT + g)*4);
                cls = gcls[b*NGT + g];
                float h  = p.z - p.x,  w  = p.w - p.y;
                float cy = p.x + 0.5f*h, cx = p.y + 0.5f*w;
                float gh = gb.z - gb.x, gw = gb.w - gb.y;
                float gcy = gb.x + 0.5f*gh, gcx = gb.y + 0.5f*gw;
                d0 = __fdiv_rn(__fdiv_rn(gcy - cy, h), stddev[0]);
                d1 = __fdiv_rn(__fdiv_rn(gcx - cx, w), stddev[1]);
                d2 = __fdiv_rn(logf(__fdiv_rn(gh, h)), stddev[2]);
                d3 = __fdiv_rn(logf(__fdiv_rn(gw, w)), stddev[3]);
            }
            out[CLS_OFF + b*NROI + t] = (float)cls;
            float* d = out + DEL_OFF + (size_t)(b*NROI + t)*4;
            d[0] = d0; d[1] = d1; d[2] = d2; d[3] = d3;

            g_posbox[(b*NPOS + t)*4 + 0] = p.x;
            g_posbox[(b*NPOS + t)*4 + 1] = p.y;
            g_posbox[(b*NPOS + t)*4 + 2] = p.z;
            g_posbox[(b*NPOS + t)*4 + 3] = p.w;
            g_posgt[b*NPOS + t] = valid ? g : -1;
        }
    } else {
        // ---- negatives: slots [66,200) ----
        int P = min(scnt, NPOS);
        // XLA rewrites x / const -> x * (1/const). fl32(1/0.33f):
        const float recip033 = 3.03030300140380859375f;
        float nnf = __fmul_rn((float)P, recip033);
        int needed = (int)nnf - P;                  // trunc toward zero (astype int32)
        needed = min(max(needed, 0), NNEG);
        for (int t = tid; t < NNEG; t += 512) {
            unsigned long long key = sk[t];
            bool valid = ((uint32_t)(key >> 32) > 0x80000000u) && (t < needed);
            int  idx   = (int)(0xFFFFFFFFu - (uint32_t)key);
            float4 p = make_float4(0.f, 0.f, 0.f, 0.f);
            if (valid) p = *reinterpret_cast<const float4*>(prop + (size_t)(b*NPROP + idx)*4);
            int slot = NPOS + t;
            float* rr = out + ROIS_OFF + (size_t)(b*NROI + slot)*4;
            rr[0] = p.x; rr[1] = p.y; rr[2] = p.z; rr[3] = p.w;
            out[CLS_OFF + b*NROI + slot] = 0.f;
            float* d = out + DEL_OFF + (size_t)(b*NROI + slot)*4;
            d[0] = 0.f; d[1] = 0.f; d[2] = 0.f; d[3] = 0.f;
        }
    }
}

// ---------------- Kernel 2: mask crop_and_resize ----------------
__global__ void k_mask(const float* __restrict__ masks, float* __restrict__ out) {
    int b = blockIdx.y, slot = blockIdx.x;
    float* o = out + MSK_OFF + (size_t)(b*NROI + slot)*(MH*MW);
    int g = -1;
    float y1 = 0.f, x1 = 0.f, y2 = 0.f, x2 = 0.f;
    if (slot < NPOS) {
        g  = g_posgt[b*NPOS + slot];
        y1 = g_posbox[(b*NPOS + slot)*4 + 0];
        x1 = g_posbox[(b*NPOS + slot)*4 + 1];
        y2 = g_posbox[(b*NPOS + slot)*4 + 2];
        x2 = g_posbox[(b*NPOS + slot)*4 + 3];
    }
    if (g < 0) {
        for (int p = threadIdx.x; p < MH*MW; p += blockDim.x) o[p] = 0.f;
        return;
    }
    const float* img = masks + (size_t)b*HH*WW*NGT + g;
    for (int p = threadIdx.x; p < MH*MW; p += blockDim.x) {
        int i = p / MW, j = p % MW;
        float ty = __fdiv_rn((float)i, (float)(MH - 1));
        float tx = __fdiv_rn((float)j, (float)(MW - 1));
        float ys = (y1 + ty * (y2 - y1)) * (float)(HH - 1);
        float xs = (x1 + tx * (x2 - x1)) * (float)(WW - 1);
        float y0f = floorf(ys), x0f = floorf(xs);
        float fy = ys - y0f,    fx = xs - x0f;
        int y0  = min(max((int)y0f, 0), HH - 1);
        int y1i = min(y0 + 1, HH - 1);
        int x0  = min(max((int)x0f, 0), WW - 1);
        int x1i = min(x0 + 1, WW - 1);
        float m00 = __ldg(img + ((size_t)y0 *WW + x0 )*NGT);
        float m01 = __ldg(img + ((size_t)y0 *WW + x1i)*NGT);
        float m10 = __ldg(img + ((size_t)y1i*WW + x0 )*NGT);
        float m11 = __ldg(img + ((size_t)y1i*WW + x1i)*NGT);
        float v = m00*(1.f-fy)*(1.f-fx) + m01*(1.f-fy)*fx
                + m10*fy*(1.f-fx)       + m11*fy*fx;
        o[p] = rintf(v);   // jnp.round = round half to even
    }
}

// ---------------- launch ----------------
extern "C" void kernel_launch(void* const* d_in, const int* in_sizes, int n_in,
                              void* d_out, int out_size) {
    (void)in_sizes; (void)n_in; (void)out_size;
    const float* prop   = (const float*)d_in[0];
    const int*   cls    = (const int*)  d_in[1];
    const float* gbox   = (const float*)d_in[2];
    const float* masks  = (const float*)d_in[3];
    const float* stddev = (const float*)d_in[4];
    float* out = (float*)d_out;

    k_iou   <<<dim3(32, NB),   256>>>(prop, cls, gbox);   // 64 proposals/block, 4 lanes each
    k_sample<<<dim3(NB, 2),    512>>>(prop, cls, gbox, stddev, out);
    k_mask  <<<dim3(NROI, NB), 256>>>(masks, out);
}